// round 9
// baseline (speedup 1.0000x reference)
#include <cuda_runtime.h>
#include <cstdint>

#define NPTS    6890
#define BF      20670           // floats per batch per tensor
#define THREADS 512
#define NWARPS  16
#define CHUNK   2496            // ring-slot floats (9984 B; mult of 12 & 16B)
#define NB      3               // gt ring depth
#define F_LOAD  20672           // padded stream length (covers pad 0 or 2)
#define NC      9               // chunks per batch (ceil(20672/2496))
#define NU      3445            // 6-float units (2 points each)

// smem layout (float offsets); 113800 B/CTA -> 2 CTAs/SM
#define SM_PRED 0                            // 20672 floats, resident pred (becomes out)
#define SM_GTR  20672                        // gt ring: 3*2496 = 7488
#define SM_RED  28160                        // NWARPS*16 = 256
#define SM_STAT 28416                        // 16
#define SM_PRM  28432                        // 12
#define SM_MBAR 28444                        // byte 113776, 8B aligned; 3 mbarriers
#define SMEM_FLOATS (SM_MBAR + 6)
#define SMEM_BYTES  (SMEM_FLOATS * 4)

__device__ __forceinline__ uint32_t smem_addr(const void* p) {
    return (uint32_t)__cvta_generic_to_shared(p);
}

__device__ __forceinline__ void mbar_wait(uint32_t mbarA, uint32_t parity) {
    uint32_t done = 0;
    while (!done) {
        asm volatile("{\n\t.reg .pred p;\n\t"
                     "mbarrier.try_wait.parity.acquire.cta.shared::cta.b64 p, [%1], %2, 0x989680;\n\t"
                     "selp.b32 %0, 1, 0, p;\n\t}"
                     : "=r"(done) : "r"(mbarA), "r"(parity) : "memory");
    }
}

// chunk boundary in padded-stream float coords
__device__ __forceinline__ int Eof(int c, int EF) {
    if (c <= 0) return 0;
    int e = EF + (c - 1) * CHUNK;
    return e < F_LOAD ? e : F_LOAD;
}

// pass A: pred chunk -> resident position, gt chunk -> ring slot (one mbarrier)
__device__ __forceinline__ void issue_load_A(int c, int EF,
                                             const float* srcP, const float* srcG,
                                             float* predS, float* gtR, uint32_t mbar0,
                                             uint64_t polP, uint64_t polG) {
    int e0 = Eof(c, EF), e1 = Eof(c + 1, EF);
    uint32_t bytes = (uint32_t)(e1 - e0) * 4u;
    uint32_t mb = mbar0 + 8u * (uint32_t)(c % NB);
    asm volatile("mbarrier.arrive.expect_tx.shared.b64 _, [%0], %1;"
                 :: "r"(mb), "r"(2u * bytes) : "memory");
    asm volatile("cp.async.bulk.shared::cluster.global.mbarrier::complete_tx::bytes.L2::cache_hint"
                 " [%0], [%1], %2, [%3], %4;"
                 :: "r"(smem_addr(predS + e0)), "l"(srcP + e0), "r"(bytes), "r"(mb), "l"(polP) : "memory");
    asm volatile("cp.async.bulk.shared::cluster.global.mbarrier::complete_tx::bytes.L2::cache_hint"
                 " [%0], [%1], %2, [%3], %4;"
                 :: "r"(smem_addr(gtR + (c % NB) * CHUNK)), "l"(srcG + e0), "r"(bytes), "r"(mb), "l"(polG) : "memory");
}

// pass B: gt chunk only -> ring slot
__device__ __forceinline__ void issue_load_B(int c, int EF,
                                             const float* srcG,
                                             float* gtR, uint32_t mbar0, uint64_t polG) {
    int e0 = Eof(c, EF), e1 = Eof(c + 1, EF);
    uint32_t bytes = (uint32_t)(e1 - e0) * 4u;
    uint32_t mb = mbar0 + 8u * (uint32_t)(c % NB);
    asm volatile("mbarrier.arrive.expect_tx.shared.b64 _, [%0], %1;"
                 :: "r"(mb), "r"(bytes) : "memory");
    asm volatile("cp.async.bulk.shared::cluster.global.mbarrier::complete_tx::bytes.L2::cache_hint"
                 " [%0], [%1], %2, [%3], %4;"
                 :: "r"(smem_addr(gtR + (c % NB) * CHUNK)), "l"(srcG + e0), "r"(bytes), "r"(mb), "l"(polG) : "memory");
}

__device__ __forceinline__ void accum_pt(float* a,
                                         float p0, float p1, float p2,
                                         float g0, float g1, float g2) {
    a[0] += p0; a[1] += p1; a[2] += p2;
    a[3] += g0; a[4] += g1; a[5] += g2;
    a[6] = fmaf(p0, p0, fmaf(p1, p1, fmaf(p2, p2, a[6])));
    a[7]  = fmaf(p0, g0, a[7]);
    a[8]  = fmaf(p0, g1, a[8]);
    a[9]  = fmaf(p0, g2, a[9]);
    a[10] = fmaf(p1, g0, a[10]);
    a[11] = fmaf(p1, g1, a[11]);
    a[12] = fmaf(p1, g2, a[12]);
    a[13] = fmaf(p2, g0, a[13]);
    a[14] = fmaf(p2, g1, a[14]);
    a[15] = fmaf(p2, g2, a[15]);
}

__global__ void __launch_bounds__(THREADS, 2)
procrustes_l1_kernel(const float* __restrict__ pred,
                     const float* __restrict__ gt,
                     float* __restrict__ out) {
    extern __shared__ float sm[];
    float* predS = sm + SM_PRED;
    float* gtR   = sm + SM_GTR;
    float* redS  = sm + SM_RED;
    float* statS = sm + SM_STAT;
    float* prm   = sm + SM_PRM;

    const int tid = threadIdx.x;
    const int b = (int)blockIdx.x;
    const size_t gstart = (size_t)b * BF;
    const int pad = (int)(gstart & 3);          // 0 (even b) or 2 (odd b)
    const int EF = pad ? (CHUNK - 4) : CHUNK;   // keeps boundaries ≡ pad (mod 6) and ≡0 (mod 4)

    const float* srcP = pred + (gstart - (size_t)pad);
    const float* srcG = gt   + (gstart - (size_t)pad);
    const uint32_t mbar0 = smem_addr(sm + SM_MBAR);

    uint64_t polLast, polFirst;
    asm volatile("createpolicy.fractional.L2::evict_last.b64 %0, 1.0;"  : "=l"(polLast));
    asm volatile("createpolicy.fractional.L2::evict_first.b64 %0, 1.0;" : "=l"(polFirst));

    if (tid == 0) {
#pragma unroll
        for (int s = 0; s < NB; s++)
            asm volatile("mbarrier.init.shared.b64 [%0], 1;" :: "r"(mbar0 + 8u * s) : "memory");
    }
    __syncthreads();

    // prologue: fill the ring (pred -> resident, gt -> ring; gt tagged evict_last)
    if (tid == 0) {
#pragma unroll
        for (int c = 0; c < NB; c++)
            issue_load_A(c, EF, srcP, srcG, predS, gtR, mbar0, polFirst, polLast);
    }

    // ---------------- Pass A: streamed 16-value reduction ----------------
    float acc[16];
#pragma unroll
    for (int i = 0; i < 16; i++) acc[i] = 0.f;

    for (int c = 0; c < NC; c++) {
        mbar_wait(mbar0 + 8u * (c % NB), (uint32_t)((c / NB) & 1));
        int e0 = Eof(c, EF), e1 = Eof(c + 1, EF);
        const float* gc = gtR + (c % NB) * CHUNK - e0;
        int uS = (e0 - pad + 5) / 6;
        int uE = (e1 - pad) / 6; if (uE > NU) uE = NU;
        for (int u = uS + tid; u < uE; u += THREADS) {
            int l = pad + 6 * u;
            float2 pa = *(const float2*)(predS + l);
            float2 pb = *(const float2*)(predS + l + 2);
            float2 pcc = *(const float2*)(predS + l + 4);
            float2 ga = *(const float2*)(gc + l);
            float2 gb = *(const float2*)(gc + l + 2);
            float2 gcc = *(const float2*)(gc + l + 4);
            accum_pt(acc, pa.x, pa.y, pb.x, ga.x, ga.y, gb.x);
            accum_pt(acc, pb.y, pcc.x, pcc.y, gb.y, gcc.x, gcc.y);
        }
        __syncthreads();
        if (tid == 0 && c + NB < NC)
            issue_load_A(c + NB, EF, srcP, srcG, predS, gtR, mbar0, polFirst, polLast);
    }

    // prefetch pass-B gt chunks 0..2 (complete during reduction + solve); evict_first now
    if (tid == 0) {
#pragma unroll
        for (int c = 0; c < NB; c++)
            issue_load_B(c, EF, srcG, gtR, mbar0, polFirst);
    }

    // warp + block reduction of the 16 stats
#pragma unroll
    for (int i = 0; i < 16; i++) {
        float v = acc[i];
        v += __shfl_down_sync(0xffffffffu, v, 16);
        v += __shfl_down_sync(0xffffffffu, v, 8);
        v += __shfl_down_sync(0xffffffffu, v, 4);
        v += __shfl_down_sync(0xffffffffu, v, 2);
        v += __shfl_down_sync(0xffffffffu, v, 1);
        acc[i] = v;
    }
    const int lane = tid & 31;
    const int wp = tid >> 5;
    if (lane == 0) {
#pragma unroll
        for (int i = 0; i < 16; i++) redS[wp * 16 + i] = acc[i];
    }
    __syncthreads();
    if (tid < 16) {
        float s = redS[tid];
#pragma unroll
        for (int w = 1; w < NWARPS; w++) s += redS[w * 16 + tid];
        statS[tid] = s;
    }
    __syncthreads();

    // ---------------- Thread 0: 3x3 Procrustes solve (overflow-safe fp32 Jacobi) ----
    if (tid == 0) {
        const float fN = (float)NPTS;
        const float invN = 1.0f / fN;
        float mu1[3], mu2[3];
#pragma unroll
        for (int i = 0; i < 3; i++) { mu1[i] = statS[i] * invN; mu2[i] = statS[3 + i] * invN; }

        float K[3][3];
#pragma unroll
        for (int i = 0; i < 3; i++)
#pragma unroll
            for (int j = 0; j < 3; j++)
                K[i][j] = statS[7 + 3 * i + j] - fN * mu1[i] * mu2[j] + 1e-8f;

        float var1 = statS[6] - fN * (mu1[0]*mu1[0] + mu1[1]*mu1[1] + mu1[2]*mu1[2]);

        float A[3][3];
#pragma unroll
        for (int i = 0; i < 3; i++)
#pragma unroll
            for (int j = 0; j < 3; j++)
                A[i][j] = K[0][i]*K[0][j] + K[1][i]*K[1][j] + K[2][i]*K[2][j];

        float V[3][3] = { {1.f,0.f,0.f}, {0.f,1.f,0.f}, {0.f,0.f,1.f} };

        for (int sweep = 0; sweep < 6; sweep++) {
#pragma unroll
            for (int pair = 0; pair < 3; pair++) {
                int p = (pair == 2) ? 1 : 0;
                int q = (pair == 0) ? 1 : 2;
                float apq = A[p][q];
                if (fabsf(apq) > 1e-18f) {
                    float tau = (A[q][q] - A[p][p]) / (2.f * apq);
                    float tt = copysignf(1.f, tau) / (fabsf(tau) + sqrtf(fmaf(tau, tau, 1.f)));
                    float c = rsqrtf(fmaf(tt, tt, 1.f));
                    float s = tt * c;
#pragma unroll
                    for (int k = 0; k < 3; k++) {
                        float akp = A[k][p], akq = A[k][q];
                        A[k][p] = c*akp - s*akq;
                        A[k][q] = s*akp + c*akq;
                    }
#pragma unroll
                    for (int k = 0; k < 3; k++) {
                        float apk = A[p][k], aqk = A[q][k];
                        A[p][k] = c*apk - s*aqk;
                        A[q][k] = s*apk + c*aqk;
                    }
#pragma unroll
                    for (int k = 0; k < 3; k++) {
                        float vkp = V[k][p], vkq = V[k][q];
                        V[k][p] = c*vkp - s*vkq;
                        V[k][q] = s*vkp + c*vkq;
                    }
                }
            }
        }

        float dd[3] = { A[0][0], A[1][1], A[2][2] };
        int oo[3] = { 0, 1, 2 };
        if (dd[oo[0]] < dd[oo[1]]) { int t = oo[0]; oo[0] = oo[1]; oo[1] = t; }
        if (dd[oo[0]] < dd[oo[2]]) { int t = oo[0]; oo[0] = oo[2]; oo[2] = t; }
        if (dd[oo[1]] < dd[oo[2]]) { int t = oo[1]; oo[1] = oo[2]; oo[2] = t; }

        float v0[3], v1[3], v2[3];
#pragma unroll
        for (int i = 0; i < 3; i++) { v0[i] = V[i][oo[0]]; v1[i] = V[i][oo[1]]; v2[i] = V[i][oo[2]]; }
        float det =
            v0[0]*(v1[1]*v2[2] - v1[2]*v2[1]) -
            v0[1]*(v1[0]*v2[2] - v1[2]*v2[0]) +
            v0[2]*(v1[0]*v2[1] - v1[1]*v2[0]);
        if (det < 0.f) { v2[0] = -v2[0]; v2[1] = -v2[1]; v2[2] = -v2[2]; }

        float Kv0[3], Kv1[3];
#pragma unroll
        for (int i = 0; i < 3; i++) {
            Kv0[i] = K[i][0]*v0[0] + K[i][1]*v0[1] + K[i][2]*v0[2];
            Kv1[i] = K[i][0]*v1[0] + K[i][1]*v1[1] + K[i][2]*v1[2];
        }
        float r0 = rsqrtf(Kv0[0]*Kv0[0] + Kv0[1]*Kv0[1] + Kv0[2]*Kv0[2] + 1e-30f);
        float u0[3] = { Kv0[0]*r0, Kv0[1]*r0, Kv0[2]*r0 };
        float d01 = u0[0]*Kv1[0] + u0[1]*Kv1[1] + u0[2]*Kv1[2];
        float u1r[3] = { Kv1[0]-d01*u0[0], Kv1[1]-d01*u0[1], Kv1[2]-d01*u0[2] };
        float r1 = rsqrtf(u1r[0]*u1r[0] + u1r[1]*u1r[1] + u1r[2]*u1r[2] + 1e-30f);
        float u1[3] = { u1r[0]*r1, u1r[1]*r1, u1r[2]*r1 };
        float w[3] = { u0[1]*u1[2] - u0[2]*u1[1],
                       u0[2]*u1[0] - u0[0]*u1[2],
                       u0[0]*u1[1] - u0[1]*u1[0] };

        float R[3][3];
#pragma unroll
        for (int i = 0; i < 3; i++)
#pragma unroll
            for (int j = 0; j < 3; j++)
                R[i][j] = v0[i]*u0[j] + v1[i]*u1[j] + v2[i]*w[j];

        float tr = 0.f;
#pragma unroll
        for (int i = 0; i < 3; i++)
#pragma unroll
            for (int j = 0; j < 3; j++)
                tr += R[i][j] * K[j][i];
        float scale = tr / var1;

#pragma unroll
        for (int i = 0; i < 3; i++)
#pragma unroll
            for (int j = 0; j < 3; j++)
                R[i][j] *= scale;
#pragma unroll
        for (int i = 0; i < 3; i++)
            prm[9 + i] = mu2[i] - (R[i][0]*mu1[0] + R[i][1]*mu1[1] + R[i][2]*mu1[2]);
#pragma unroll
        for (int i = 0; i < 3; i++)
#pragma unroll
            for (int j = 0; j < 3; j++)
                prm[3 * i + j] = R[i][j];
    }
    __syncthreads();

    // ---------------- Pass B: in-place transform of resident pred + TMA store --------
    float Rs[9], tv[3];
#pragma unroll
    for (int i = 0; i < 9; i++) Rs[i] = prm[i];
    tv[0] = prm[9]; tv[1] = prm[10]; tv[2] = prm[11];

    const int tailAligned = (pad + BF) & ~3;

    for (int c = 0; c < NC; c++) {
        // slot c%NB had 3 uses in pass A -> pass-B wait parity = (3 + c/NB) & 1
        mbar_wait(mbar0 + 8u * (c % NB), (uint32_t)((3 + c / NB) & 1));
        int e0 = Eof(c, EF), e1 = Eof(c + 1, EF);
        const float* gc = gtR + (c % NB) * CHUNK - e0;
        int uS = (e0 - pad + 5) / 6;
        int uE = (e1 - pad) / 6; if (uE > NU) uE = NU;
        for (int u = uS + tid; u < uE; u += THREADS) {
            int l = pad + 6 * u;
            float2 pa = *(const float2*)(predS + l);
            float2 pb = *(const float2*)(predS + l + 2);
            float2 pcc = *(const float2*)(predS + l + 4);
            float2 ga = *(const float2*)(gc + l);
            float2 gb = *(const float2*)(gc + l + 2);
            float2 gcc = *(const float2*)(gc + l + 4);

            float p0x = pa.x, p0y = pa.y, p0z = pb.x;
            float p1x = pb.y, p1y = pcc.x, p1z = pcc.y;

            float o0x = fabsf(fmaf(Rs[0], p0x, fmaf(Rs[1], p0y, fmaf(Rs[2], p0z, tv[0]))) - ga.x);
            float o0y = fabsf(fmaf(Rs[3], p0x, fmaf(Rs[4], p0y, fmaf(Rs[5], p0z, tv[1]))) - ga.y);
            float o0z = fabsf(fmaf(Rs[6], p0x, fmaf(Rs[7], p0y, fmaf(Rs[8], p0z, tv[2]))) - gb.x);
            float o1x = fabsf(fmaf(Rs[0], p1x, fmaf(Rs[1], p1y, fmaf(Rs[2], p1z, tv[0]))) - gb.y);
            float o1y = fabsf(fmaf(Rs[3], p1x, fmaf(Rs[4], p1y, fmaf(Rs[5], p1z, tv[1]))) - gcc.x);
            float o1z = fabsf(fmaf(Rs[6], p1x, fmaf(Rs[7], p1y, fmaf(Rs[8], p1z, tv[2]))) - gcc.y);

            *(float2*)(predS + l)     = make_float2(o0x, o0y);
            *(float2*)(predS + l + 2) = make_float2(o0z, o1x);
            *(float2*)(predS + l + 4) = make_float2(o1y, o1z);
        }
        __syncthreads();
        if (tid == 0) {
            asm volatile("fence.proxy.async.shared::cta;" ::: "memory");
            int sl0 = (c == 0 && pad) ? 4 : e0;             // skip front misaligned floats
            int sl1 = e1 < tailAligned ? e1 : tailAligned;  // trim tail
            uint32_t sb = (uint32_t)(sl1 - sl0) * 4u;
            asm volatile("cp.async.bulk.global.shared::cta.bulk_group.L2::cache_hint [%0], [%1], %2, %3;"
                         :: "l"(out + gstart - (size_t)pad + sl0),
                            "r"(smem_addr(predS + sl0)), "r"(sb), "l"(polFirst) : "memory");
            asm volatile("cp.async.bulk.commit_group;" ::: "memory");
            if (c == 0 && pad) {                            // elements 0,1 live at predS[2],[3]
                out[gstart]     = predS[2];
                out[gstart + 1] = predS[3];
            }
            if (c == NC - 1 && !pad) {                      // tail elements 20668,20669
                out[gstart + BF - 2] = predS[BF - 2];
                out[gstart + BF - 1] = predS[BF - 1];
            }
            // no store-drain needed: stores read predS (never reloaded); ring reload writes gtR
            if (c + NB < NC) issue_load_B(c + NB, EF, srcG, gtR, mbar0, polFirst);
        }
    }
    if (tid == 0) {
        asm volatile("cp.async.bulk.wait_group 0;" ::: "memory");
    }
}

extern "C" void kernel_launch(void* const* d_in, const int* in_sizes, int n_in,
                              void* d_out, int out_size) {
    const float* pred = (const float*)d_in[0];
    const float* gt   = (const float*)d_in[1];
    float* out = (float*)d_out;
    int B = in_sizes[0] / BF;   // 1024

    cudaFuncSetAttribute(procrustes_l1_kernel,
                         cudaFuncAttributeMaxDynamicSharedMemorySize, SMEM_BYTES);
    procrustes_l1_kernel<<<B, THREADS, SMEM_BYTES>>>(pred, gt, out);
}

// round 11
// speedup vs baseline: 1.0960x; 1.0960x over previous
#include <cuda_runtime.h>
#include <cstdint>

#define NPTS    6890
#define BF      20670           // floats per batch per tensor
#define THREADS 256
#define NWARPS  8
#define CHUNK   1560            // ring-slot floats (6240 B; mult of 12 & 16B)
#define NB      3               // ring depth (per tensor) and out-staging depth
#define F_LOAD  20672           // padded stream length (covers pad 0 or 2)
#define NC      14              // chunks per batch (ceil(20672/1560))
#define NU      3445            // 6-float units (2 points each)

// smem layout (float offsets); 56808 B/CTA -> 4 CTAs/SM
#define SM_PRED 0                            // 3*1560 = 4680
#define SM_GT   4680                         // 4680
#define SM_OUT  9360                         // 4680 (out staging, decoupled from ring)
#define SM_RED  14040                        // NWARPS*16 = 128
#define SM_STAT 14168                        // 16
#define SM_PRM  14184                        // 12
#define SM_MBAR 14196                        // byte 56784, 8B aligned; 3 mbarriers
#define SMEM_FLOATS (SM_MBAR + 6)
#define SMEM_BYTES  (SMEM_FLOATS * 4)

__device__ __forceinline__ uint32_t smem_addr(const void* p) {
    return (uint32_t)__cvta_generic_to_shared(p);
}

__device__ __forceinline__ void mbar_wait(uint32_t mbarA, uint32_t parity) {
    uint32_t done = 0;
    while (!done) {
        asm volatile("{\n\t.reg .pred p;\n\t"
                     "mbarrier.try_wait.parity.acquire.cta.shared::cta.b64 p, [%1], %2, 0x989680;\n\t"
                     "selp.b32 %0, 1, 0, p;\n\t}"
                     : "=r"(done) : "r"(mbarA), "r"(parity) : "memory");
    }
}

// chunk boundary in padded-stream float coords
__device__ __forceinline__ int Eof(int c, int EF) {
    if (c <= 0) return 0;
    int e = EF + (c - 1) * CHUNK;
    return e < F_LOAD ? e : F_LOAD;
}

// load pred chunk + gt chunk into ring slot c%NB (one mbarrier), with L2 policy
__device__ __forceinline__ void issue_load(int c, int EF,
                                           const float* srcP, const float* srcG,
                                           float* predR, float* gtR, uint32_t mbar0,
                                           uint64_t pol) {
    int e0 = Eof(c, EF), e1 = Eof(c + 1, EF);
    uint32_t bytes = (uint32_t)(e1 - e0) * 4u;
    uint32_t mb = mbar0 + 8u * (uint32_t)(c % NB);
    asm volatile("mbarrier.arrive.expect_tx.shared.b64 _, [%0], %1;"
                 :: "r"(mb), "r"(2u * bytes) : "memory");
    asm volatile("cp.async.bulk.shared::cluster.global.mbarrier::complete_tx::bytes.L2::cache_hint"
                 " [%0], [%1], %2, [%3], %4;"
                 :: "r"(smem_addr(predR + (c % NB) * CHUNK)), "l"(srcP + e0), "r"(bytes), "r"(mb), "l"(pol) : "memory");
    asm volatile("cp.async.bulk.shared::cluster.global.mbarrier::complete_tx::bytes.L2::cache_hint"
                 " [%0], [%1], %2, [%3], %4;"
                 :: "r"(smem_addr(gtR + (c % NB) * CHUNK)), "l"(srcG + e0), "r"(bytes), "r"(mb), "l"(pol) : "memory");
}

__device__ __forceinline__ void accum_pt(float* a,
                                         float p0, float p1, float p2,
                                         float g0, float g1, float g2) {
    a[0] += p0; a[1] += p1; a[2] += p2;
    a[3] += g0; a[4] += g1; a[5] += g2;
    a[6] = fmaf(p0, p0, fmaf(p1, p1, fmaf(p2, p2, a[6])));
    a[7]  = fmaf(p0, g0, a[7]);
    a[8]  = fmaf(p0, g1, a[8]);
    a[9]  = fmaf(p0, g2, a[9]);
    a[10] = fmaf(p1, g0, a[10]);
    a[11] = fmaf(p1, g1, a[11]);
    a[12] = fmaf(p1, g2, a[12]);
    a[13] = fmaf(p2, g0, a[13]);
    a[14] = fmaf(p2, g1, a[14]);
    a[15] = fmaf(p2, g2, a[15]);
}

__global__ void __launch_bounds__(THREADS, 4)
procrustes_l1_kernel(const float* __restrict__ pred,
                     const float* __restrict__ gt,
                     float* __restrict__ out) {
    extern __shared__ float sm[];
    float* predR = sm + SM_PRED;
    float* gtR   = sm + SM_GT;
    float* outR  = sm + SM_OUT;
    float* redS  = sm + SM_RED;
    float* statS = sm + SM_STAT;
    float* prm   = sm + SM_PRM;

    const int tid = threadIdx.x;
    const int b = (int)blockIdx.x;
    const size_t gstart = (size_t)b * BF;
    const int pad = (int)(gstart & 3);          // 0 (even b) or 2 (odd b)
    const int EF = pad ? (CHUNK - 4) : CHUNK;   // keeps boundaries ≡ pad (mod 6), ≡ 0 (mod 4)

    const float* srcP = pred + (gstart - (size_t)pad);
    const float* srcG = gt   + (gstart - (size_t)pad);
    const uint32_t mbar0 = smem_addr(sm + SM_MBAR);

    uint64_t polLast, polFirst;
    asm volatile("createpolicy.fractional.L2::evict_last.b64 %0, 1.0;"  : "=l"(polLast));
    asm volatile("createpolicy.fractional.L2::evict_first.b64 %0, 1.0;" : "=l"(polFirst));

    if (tid == 0) {
#pragma unroll
        for (int s = 0; s < NB; s++)
            asm volatile("mbarrier.init.shared.b64 [%0], 1;" :: "r"(mbar0 + 8u * s) : "memory");
    }
    __syncthreads();

    // prologue: fill the ring (pass-A loads protected in L2 for the pass-B reload)
    if (tid == 0) {
#pragma unroll
        for (int c = 0; c < NB; c++)
            issue_load(c, EF, srcP, srcG, predR, gtR, mbar0, polLast);
    }

    // ---------------- Pass A: streamed 16-value reduction ----------------
    float acc[16];
#pragma unroll
    for (int i = 0; i < 16; i++) acc[i] = 0.f;

    for (int c = 0; c < NC; c++) {
        mbar_wait(mbar0 + 8u * (c % NB), (uint32_t)((c / NB) & 1));
        int e0 = Eof(c, EF), e1 = Eof(c + 1, EF);
        const float* pc = predR + (c % NB) * CHUNK - e0;
        const float* gc = gtR   + (c % NB) * CHUNK - e0;
        int uS = (e0 - pad + 5) / 6;
        int uE = (e1 - pad) / 6; if (uE > NU) uE = NU;
        for (int u = uS + tid; u < uE; u += THREADS) {
            int l = pad + 6 * u;
            float2 pa = *(const float2*)(pc + l);
            float2 pb = *(const float2*)(pc + l + 2);
            float2 pcc = *(const float2*)(pc + l + 4);
            float2 ga = *(const float2*)(gc + l);
            float2 gb = *(const float2*)(gc + l + 2);
            float2 gcc = *(const float2*)(gc + l + 4);
            accum_pt(acc, pa.x, pa.y, pb.x, ga.x, ga.y, gb.x);
            accum_pt(acc, pb.y, pcc.x, pcc.y, gb.y, gcc.x, gcc.y);
        }
        __syncthreads();
        if (tid == 0 && c + NB < NC)
            issue_load(c + NB, EF, srcP, srcG, predR, gtR, mbar0, polLast);
    }

    // prefetch pass-B chunks 0..2 (complete during reduction + solve); one-shot now
    if (tid == 0) {
#pragma unroll
        for (int c = 0; c < NB; c++)
            issue_load(c, EF, srcP, srcG, predR, gtR, mbar0, polFirst);
    }

    // warp + block reduction of the 16 stats
#pragma unroll
    for (int i = 0; i < 16; i++) {
        float v = acc[i];
        v += __shfl_down_sync(0xffffffffu, v, 16);
        v += __shfl_down_sync(0xffffffffu, v, 8);
        v += __shfl_down_sync(0xffffffffu, v, 4);
        v += __shfl_down_sync(0xffffffffu, v, 2);
        v += __shfl_down_sync(0xffffffffu, v, 1);
        acc[i] = v;
    }
    const int lane = tid & 31;
    const int wp = tid >> 5;
    if (lane == 0) {
#pragma unroll
        for (int i = 0; i < 16; i++) redS[wp * 16 + i] = acc[i];
    }
    __syncthreads();
    if (tid < 16) {
        float s = redS[tid];
#pragma unroll
        for (int w = 1; w < NWARPS; w++) s += redS[w * 16 + tid];
        statS[tid] = s;
    }
    __syncthreads();

    // ---------------- Thread 0: 3x3 Procrustes solve (overflow-safe fp32 Jacobi) ----
    if (tid == 0) {
        const float fN = (float)NPTS;
        const float invN = 1.0f / fN;
        float mu1[3], mu2[3];
#pragma unroll
        for (int i = 0; i < 3; i++) { mu1[i] = statS[i] * invN; mu2[i] = statS[3 + i] * invN; }

        float K[3][3];
#pragma unroll
        for (int i = 0; i < 3; i++)
#pragma unroll
            for (int j = 0; j < 3; j++)
                K[i][j] = statS[7 + 3 * i + j] - fN * mu1[i] * mu2[j] + 1e-8f;

        float var1 = statS[6] - fN * (mu1[0]*mu1[0] + mu1[1]*mu1[1] + mu1[2]*mu1[2]);

        float A[3][3];
#pragma unroll
        for (int i = 0; i < 3; i++)
#pragma unroll
            for (int j = 0; j < 3; j++)
                A[i][j] = K[0][i]*K[0][j] + K[1][i]*K[1][j] + K[2][i]*K[2][j];

        float V[3][3] = { {1.f,0.f,0.f}, {0.f,1.f,0.f}, {0.f,0.f,1.f} };

        for (int sweep = 0; sweep < 6; sweep++) {
#pragma unroll
            for (int pair = 0; pair < 3; pair++) {
                int p = (pair == 2) ? 1 : 0;
                int q = (pair == 0) ? 1 : 2;
                float apq = A[p][q];
                if (fabsf(apq) > 1e-18f) {
                    float tau = (A[q][q] - A[p][p]) / (2.f * apq);
                    float tt = copysignf(1.f, tau) / (fabsf(tau) + sqrtf(fmaf(tau, tau, 1.f)));
                    float c = rsqrtf(fmaf(tt, tt, 1.f));
                    float s = tt * c;
#pragma unroll
                    for (int k = 0; k < 3; k++) {
                        float akp = A[k][p], akq = A[k][q];
                        A[k][p] = c*akp - s*akq;
                        A[k][q] = s*akp + c*akq;
                    }
#pragma unroll
                    for (int k = 0; k < 3; k++) {
                        float apk = A[p][k], aqk = A[q][k];
                        A[p][k] = c*apk - s*aqk;
                        A[q][k] = s*apk + c*aqk;
                    }
#pragma unroll
                    for (int k = 0; k < 3; k++) {
                        float vkp = V[k][p], vkq = V[k][q];
                        V[k][p] = c*vkp - s*vkq;
                        V[k][q] = s*vkp + c*vkq;
                    }
                }
            }
        }

        float dd[3] = { A[0][0], A[1][1], A[2][2] };
        int oo[3] = { 0, 1, 2 };
        if (dd[oo[0]] < dd[oo[1]]) { int t = oo[0]; oo[0] = oo[1]; oo[1] = t; }
        if (dd[oo[0]] < dd[oo[2]]) { int t = oo[0]; oo[0] = oo[2]; oo[2] = t; }
        if (dd[oo[1]] < dd[oo[2]]) { int t = oo[1]; oo[1] = oo[2]; oo[2] = t; }

        float v0[3], v1[3], v2[3];
#pragma unroll
        for (int i = 0; i < 3; i++) { v0[i] = V[i][oo[0]]; v1[i] = V[i][oo[1]]; v2[i] = V[i][oo[2]]; }
        float det =
            v0[0]*(v1[1]*v2[2] - v1[2]*v2[1]) -
            v0[1]*(v1[0]*v2[2] - v1[2]*v2[0]) +
            v0[2]*(v1[0]*v2[1] - v1[1]*v2[0]);
        if (det < 0.f) { v2[0] = -v2[0]; v2[1] = -v2[1]; v2[2] = -v2[2]; }

        float Kv0[3], Kv1[3];
#pragma unroll
        for (int i = 0; i < 3; i++) {
            Kv0[i] = K[i][0]*v0[0] + K[i][1]*v0[1] + K[i][2]*v0[2];
            Kv1[i] = K[i][0]*v1[0] + K[i][1]*v1[1] + K[i][2]*v1[2];
        }
        float r0 = rsqrtf(Kv0[0]*Kv0[0] + Kv0[1]*Kv0[1] + Kv0[2]*Kv0[2] + 1e-30f);
        float u0[3] = { Kv0[0]*r0, Kv0[1]*r0, Kv0[2]*r0 };
        float d01 = u0[0]*Kv1[0] + u0[1]*Kv1[1] + u0[2]*Kv1[2];
        float u1r[3] = { Kv1[0]-d01*u0[0], Kv1[1]-d01*u0[1], Kv1[2]-d01*u0[2] };
        float r1 = rsqrtf(u1r[0]*u1r[0] + u1r[1]*u1r[1] + u1r[2]*u1r[2] + 1e-30f);
        float u1[3] = { u1r[0]*r1, u1r[1]*r1, u1r[2]*r1 };
        float w[3] = { u0[1]*u1[2] - u0[2]*u1[1],
                       u0[2]*u1[0] - u0[0]*u1[2],
                       u0[0]*u1[1] - u0[1]*u1[0] };

        float R[3][3];
#pragma unroll
        for (int i = 0; i < 3; i++)
#pragma unroll
            for (int j = 0; j < 3; j++)
                R[i][j] = v0[i]*u0[j] + v1[i]*u1[j] + v2[i]*w[j];

        float tr = 0.f;
#pragma unroll
        for (int i = 0; i < 3; i++)
#pragma unroll
            for (int j = 0; j < 3; j++)
                tr += R[i][j] * K[j][i];
        float scale = tr / var1;

#pragma unroll
        for (int i = 0; i < 3; i++)
#pragma unroll
            for (int j = 0; j < 3; j++)
                R[i][j] *= scale;
#pragma unroll
        for (int i = 0; i < 3; i++)
            prm[9 + i] = mu2[i] - (R[i][0]*mu1[0] + R[i][1]*mu1[1] + R[i][2]*mu1[2]);
#pragma unroll
        for (int i = 0; i < 3; i++)
#pragma unroll
            for (int j = 0; j < 3; j++)
                prm[3 * i + j] = R[i][j];
    }
    __syncthreads();

    // ---------------- Pass B: streamed apply into out staging + TMA store ------------
    float Rs[9], tv[3];
#pragma unroll
    for (int i = 0; i < 9; i++) Rs[i] = prm[i];
    tv[0] = prm[9]; tv[1] = prm[10]; tv[2] = prm[11];

    const int tailAligned = (pad + BF) & ~3;

    for (int c = 0; c < NC; c++) {
        // drain old stores so out slot c%NB is free (conflicting group is c-NB; keep ≤2 outstanding)
        if (tid == 0) {
            asm volatile("cp.async.bulk.wait_group 2;" ::: "memory");
        }
        // slot c%NB pass-A uses: slot2 -> 4, others -> 5; parity = (usesA + c/NB) & 1
        uint32_t parB = (uint32_t)(((((c % NB) == 2) ? 4 : 5) + c / NB) & 1);
        mbar_wait(mbar0 + 8u * (c % NB), parB);
        __syncthreads();   // out-slot free (tid0's wait_group) visible to all before writes
        int e0 = Eof(c, EF), e1 = Eof(c + 1, EF);
        const float* pc = predR + (c % NB) * CHUNK - e0;
        const float* gc = gtR   + (c % NB) * CHUNK - e0;
        float* oc = outR + (c % NB) * CHUNK - e0;
        int uS = (e0 - pad + 5) / 6;
        int uE = (e1 - pad) / 6; if (uE > NU) uE = NU;
        for (int u = uS + tid; u < uE; u += THREADS) {
            int l = pad + 6 * u;
            float2 pa = *(const float2*)(pc + l);
            float2 pb = *(const float2*)(pc + l + 2);
            float2 pcc = *(const float2*)(pc + l + 4);
            float2 ga = *(const float2*)(gc + l);
            float2 gb = *(const float2*)(gc + l + 2);
            float2 gcc = *(const float2*)(gc + l + 4);

            float p0x = pa.x, p0y = pa.y, p0z = pb.x;
            float p1x = pb.y, p1y = pcc.x, p1z = pcc.y;

            float o0x = fabsf(fmaf(Rs[0], p0x, fmaf(Rs[1], p0y, fmaf(Rs[2], p0z, tv[0]))) - ga.x);
            float o0y = fabsf(fmaf(Rs[3], p0x, fmaf(Rs[4], p0y, fmaf(Rs[5], p0z, tv[1]))) - ga.y);
            float o0z = fabsf(fmaf(Rs[6], p0x, fmaf(Rs[7], p0y, fmaf(Rs[8], p0z, tv[2]))) - gb.x);
            float o1x = fabsf(fmaf(Rs[0], p1x, fmaf(Rs[1], p1y, fmaf(Rs[2], p1z, tv[0]))) - gb.y);
            float o1y = fabsf(fmaf(Rs[3], p1x, fmaf(Rs[4], p1y, fmaf(Rs[5], p1z, tv[1]))) - gcc.x);
            float o1z = fabsf(fmaf(Rs[6], p1x, fmaf(Rs[7], p1y, fmaf(Rs[8], p1z, tv[2]))) - gcc.y);

            *(float2*)(oc + l)     = make_float2(o0x, o0y);
            *(float2*)(oc + l + 2) = make_float2(o0z, o1x);
            *(float2*)(oc + l + 4) = make_float2(o1y, o1z);
        }
        __syncthreads();
        if (tid == 0) {
            asm volatile("fence.proxy.async.shared::cta;" ::: "memory");
            int sl0 = (c == 0 && pad) ? 4 : e0;             // skip front misaligned floats
            int sl1 = e1 < tailAligned ? e1 : tailAligned;  // trim tail
            uint32_t sb = (uint32_t)(sl1 - sl0) * 4u;
            float* slotBase = outR + (c % NB) * CHUNK;
            asm volatile("cp.async.bulk.global.shared::cta.bulk_group.L2::cache_hint [%0], [%1], %2, %3;"
                         :: "l"(out + gstart - (size_t)pad + sl0),
                            "r"(smem_addr(slotBase + (sl0 - e0))), "r"(sb), "l"(polFirst) : "memory");
            asm volatile("cp.async.bulk.commit_group;" ::: "memory");
            if (c == 0 && pad) {                            // elements 0,1 at stream l=2,3
                out[gstart]     = slotBase[2];
                out[gstart + 1] = slotBase[3];
            }
            if (c == NC - 1 && !pad) {                      // tail elements 20668,20669
                out[gstart + BF - 2] = slotBase[(pad + BF - 2) - e0];
                out[gstart + BF - 1] = slotBase[(pad + BF - 1) - e0];
            }
            // ring reload: loads write predR/gtR slots, stores read outR -> no conflict
            if (c + NB < NC) issue_load(c + NB, EF, srcP, srcG, predR, gtR, mbar0, polFirst);
        }
    }
    if (tid == 0) {
        asm volatile("cp.async.bulk.wait_group 0;" ::: "memory");
    }
}

extern "C" void kernel_launch(void* const* d_in, const int* in_sizes, int n_in,
                              void* d_out, int out_size) {
    const float* pred = (const float*)d_in[0];
    const float* gt   = (const float*)d_in[1];
    float* out = (float*)d_out;
    int B = in_sizes[0] / BF;   // 1024

    cudaFuncSetAttribute(procrustes_l1_kernel,
                         cudaFuncAttributeMaxDynamicSharedMemorySize, SMEM_BYTES);
    procrustes_l1_kernel<<<B, THREADS, SMEM_BYTES>>>(pred, gt, out);
}